// round 1
// baseline (speedup 1.0000x reference)
#include <cuda_runtime.h>
#include <math.h>

// Problem constants (fixed by the dataset): N=100000, E=1600000, Cin=64, H=16, Cout=16, K=5
#define NCAP 100032

// Scratch (allocation-free contract): ~173 MB of __device__ globals.
__device__ float g_y[(size_t)NCAP * 400];    // reused: y1 [N,25*16] then y2 [N,25*16]
__device__ float g_agg[(size_t)NCAP * 16];   // reused: per-layer aggregation
__device__ float g_deg[NCAP];                // in-degree (computed once)
__device__ float g_h[(size_t)NCAP * 16];     // layer-1 output (post ReLU)

__device__ __forceinline__ void red_add_v4(float* a, float4 v) {
    asm volatile("red.global.add.v4.f32 [%0], {%1, %2, %3, %4};"
                 :: "l"(a), "f"(v.x), "f"(v.y), "f"(v.z), "f"(v.w) : "memory");
}

__global__ void zero_kernel(int nAgg, int nDeg) {
    int i = blockIdx.x * blockDim.x + threadIdx.x;
    if (i < nAgg) g_agg[i] = 0.0f;
    if (i < nDeg) g_deg[i] = 0.0f;
}

// Y[n, k*16+o] = sum_i X[n,i] * W[k,i,o]
// Block: 256 threads = (tx:16 = o, ty:16 = node-group of 4). Thread tile: 4 nodes x 25 k.
// Smem: Ws[i*400 + k*16 + o] (CIN*400 floats) + Xs transposed [CIN][68] (padded, float4 reads).
template<int CIN, bool USE_H>
__global__ void __launch_bounds__(256, 1) y_kernel(const float* __restrict__ Xin,
                                                   const float* __restrict__ W, int N) {
    extern __shared__ float sm[];
    float* Ws = sm;               // CIN*400
    float* Xs = sm + CIN * 400;   // CIN*68
    const float* X = USE_H ? (const float*)g_h : Xin;

    const int tid = threadIdx.x;
    const int tx = tid & 15;      // output channel within kernel matrix
    const int ty = tid >> 4;      // node group (4 nodes each)

    // Load W (layout in gmem: [k][i][o], flat idx = (k*CIN + i)*16 + o)
    for (int idx = tid; idx < CIN * 400; idx += 256) {
        int o = idx & 15;
        int r = idx >> 4;         // k*CIN + i
        int i = r % CIN;
        int k = r / CIN;
        Ws[i * 400 + k * 16 + o] = W[idx];
    }

    const int ntiles = (N + 63) >> 6;
    for (int tile = blockIdx.x; tile < ntiles; tile += gridDim.x) {
        const int n0 = tile << 6;
        __syncthreads();  // previous-iter readers done (also orders Ws before first compute)
        // Load 64-node X tile, transposed: Xs[i*68 + node_local]
        for (int idx = tid; idx < 64 * CIN; idx += 256) {
            int i = idx % CIN;
            int nl = idx / CIN;
            int n = n0 + nl;
            Xs[i * 68 + nl] = (n < N) ? X[(size_t)n * CIN + i] : 0.0f;
        }
        __syncthreads();

        float acc[25][4];
        #pragma unroll
        for (int k = 0; k < 25; k++) {
            acc[k][0] = 0.f; acc[k][1] = 0.f; acc[k][2] = 0.f; acc[k][3] = 0.f;
        }
        const int nb = ty * 4;
        #pragma unroll 2
        for (int i = 0; i < CIN; i++) {
            float4 xv = *reinterpret_cast<const float4*>(&Xs[i * 68 + nb]);
            const float* wr = &Ws[i * 400 + tx];
            #pragma unroll
            for (int k = 0; k < 25; k++) {
                float w = wr[k * 16];
                acc[k][0] += w * xv.x;
                acc[k][1] += w * xv.y;
                acc[k][2] += w * xv.z;
                acc[k][3] += w * xv.w;
            }
        }
        #pragma unroll
        for (int r = 0; r < 4; r++) {
            int n = n0 + nb + r;
            if (n < N) {
                float* yo = g_y + (size_t)n * 400 + tx;
                #pragma unroll
                for (int k = 0; k < 25; k++) yo[k * 16] = acc[k][r];
            }
        }
    }
}

// 4 lanes per edge (q = float4-group). 4 corner gathers of float4 + one red.v4 scatter.
__global__ void edge_kernel(const int* __restrict__ src, const int* __restrict__ dst,
                            const float* __restrict__ pseudo, int E, int addDeg) {
    int t = blockIdx.x * blockDim.x + threadIdx.x;
    int e = t >> 2;
    if (e >= E) return;
    int q = t & 3;
    int s = __ldg(src + e);
    int d = __ldg(dst + e);
    float p0 = __ldg(pseudo + 2 * e);
    float p1 = __ldg(pseudo + 2 * e + 1);
    float v0 = p0 * 4.0f, v1 = p1 * 4.0f;
    float fl0 = floorf(v0), fl1 = floorf(v1);
    float f0 = v0 - fl0, f1 = v1 - fl1;
    int i0 = (int)fl0, i1 = (int)fl1;
    int i0b = i0 + 1; if (i0b >= 5) i0b = 0;
    int i1b = i1 + 1; if (i1b >= 5) i1b = 0;
    float g0 = 1.0f - f0, g1 = 1.0f - f1;
    float w00 = g0 * g1, w10 = f0 * g1, w01 = g0 * f1, w11 = f0 * f1;

    const float4* yb = reinterpret_cast<const float4*>(g_y + (size_t)s * 400);
    float4 m00 = __ldg(yb + ((i1 * 5 + i0 ) * 4 + q));
    float4 m10 = __ldg(yb + ((i1 * 5 + i0b) * 4 + q));
    float4 m01 = __ldg(yb + ((i1b * 5 + i0 ) * 4 + q));
    float4 m11 = __ldg(yb + ((i1b * 5 + i0b) * 4 + q));

    float4 m;
    m.x = w00 * m00.x + w10 * m10.x + w01 * m01.x + w11 * m11.x;
    m.y = w00 * m00.y + w10 * m10.y + w01 * m01.y + w11 * m11.y;
    m.z = w00 * m00.z + w10 * m10.z + w01 * m01.z + w11 * m11.z;
    m.w = w00 * m00.w + w10 * m10.w + w01 * m01.w + w11 * m11.w;

    red_add_v4(g_agg + (size_t)d * 16 + q * 4, m);
    if (addDeg && q == 0) atomicAdd(g_deg + d, 1.0f);
}

// out[n,o] = agg[n,o]/max(deg,1) + X[n,:] @ root[:,o] + bias[o]  (optionally ReLU -> g_h)
template<int CIN, bool USE_H, bool RELU_TO_H>
__global__ void node_kernel(const float* __restrict__ Xin, const float* __restrict__ root,
                            const float* __restrict__ bias, float* __restrict__ out, int N) {
    int t = blockIdx.x * blockDim.x + threadIdx.x;
    int n = t >> 4;
    if (n >= N) return;
    int o = t & 15;
    const float* X = USE_H ? (const float*)g_h : Xin;
    const float* xr = X + (size_t)n * CIN;
    float acc = __ldg(bias + o);
    #pragma unroll
    for (int i = 0; i < CIN; i++)
        acc += __ldg(xr + i) * __ldg(root + i * 16 + o);
    float dg = g_deg[n];
    dg = dg > 1.0f ? dg : 1.0f;
    float r = g_agg[(size_t)n * 16 + o] / dg + acc;
    if (RELU_TO_H) {
        g_h[(size_t)n * 16 + o] = r > 0.0f ? r : 0.0f;
    } else {
        out[(size_t)n * 16 + o] = r;
    }
}

extern "C" void kernel_launch(void* const* d_in, const int* in_sizes, int n_in,
                              void* d_out, int out_size) {
    const float* x      = (const float*)d_in[0];
    const int*   ei     = (const int*)  d_in[1];
    const float* pseudo = (const float*)d_in[2];
    const float* W1     = (const float*)d_in[3];
    const float* root1  = (const float*)d_in[4];
    const float* b1     = (const float*)d_in[5];
    const float* W2     = (const float*)d_in[6];
    const float* root2  = (const float*)d_in[7];
    const float* b2     = (const float*)d_in[8];
    float* out = (float*)d_out;

    int N = in_sizes[0] / 64;
    int E = in_sizes[1] / 2;
    if (N > NCAP) N = NCAP;
    const int* src = ei;
    const int* dst = ei + E;

    const int smem1 = (64 * 400 + 64 * 68) * 4;   // 119808 B
    const int smem2 = (16 * 400 + 16 * 68) * 4;   // 29952 B
    cudaFuncSetAttribute((const void*)y_kernel<64, false>,
                         cudaFuncAttributeMaxDynamicSharedMemorySize, smem1);

    int nodeGrid = (N * 16 + 255) / 256;
    int edgeGrid = (E * 4 + 255) / 256;
    int ntiles = (N + 63) / 64;
    int yGrid = ntiles < 592 ? ntiles : 592;

    // ---- Layer 1 ----
    zero_kernel<<<nodeGrid, 256>>>(N * 16, N);
    y_kernel<64, false><<<yGrid, 256, smem1>>>(x, W1, N);
    edge_kernel<<<edgeGrid, 256>>>(src, dst, pseudo, E, 1);
    node_kernel<64, false, true><<<nodeGrid, 256>>>(x, root1, b1, nullptr, N);

    // ---- Layer 2 ----
    zero_kernel<<<nodeGrid, 256>>>(N * 16, 0);
    y_kernel<16, true><<<yGrid, 256, smem2>>>(nullptr, W2, N);
    edge_kernel<<<edgeGrid, 256>>>(src, dst, pseudo, E, 0);
    node_kernel<16, true, false><<<nodeGrid, 256>>>(nullptr, root2, b2, out, N);
}

// round 2
// speedup vs baseline: 1.1570x; 1.1570x over previous
#include <cuda_runtime.h>
#include <cuda_fp16.h>
#include <math.h>

// Problem constants: N=100000, E=1600000, Cin=64, H=16, Cout=16, K=5
#define NCAP 100032

// Scratch (allocation-free contract).
__device__ __half g_y[(size_t)NCAP * 400];   // per-kernel products, fp16 (80MB -> L2 resident)
__device__ float  g_agg[(size_t)NCAP * 16];  // per-layer aggregation
__device__ float  g_deg[NCAP];               // in-degree (computed once, layer 1)
__device__ float  g_h[(size_t)NCAP * 16];    // layer-1 output (post ReLU), fp32
__device__ float  g_rt[(size_t)NCAP * 16];   // x @ root + bias (per layer)

__device__ __forceinline__ void red_add_v4(float* a, float x, float y, float z, float w) {
    asm volatile("red.global.add.v4.f32 [%0], {%1, %2, %3, %4};"
                 :: "l"(a), "f"(x), "f"(y), "f"(z), "f"(w) : "memory");
}

__global__ void zero_kernel(int nAgg, int nDeg) {
    int i = blockIdx.x * blockDim.x + threadIdx.x;
    if (i < nAgg) g_agg[i] = 0.0f;
    if (i < nDeg) g_deg[i] = 0.0f;
}

// Y[n, k*16+o] = sum_i X[n,i] * W[k,i,o]  (stored fp16)
// Also: g_rt[n,o] = sum_i X[n,i] * root[i,o] + bias[o]
// Block: 256 threads = (tx:16 = o, ty:16 = group of 4 nodes). 64-node tiles.
template<int CIN, bool USE_H>
__global__ void __launch_bounds__(256, 1) y_kernel(const float* __restrict__ Xin,
                                                   const float* __restrict__ W,
                                                   const float* __restrict__ root,
                                                   const float* __restrict__ bias, int N) {
    extern __shared__ float sm[];
    float* Ws = sm;                          // CIN*400
    float* Xs = sm + CIN * 400;              // CIN*68 (padded)
    float* Rs = Xs + CIN * 68;               // CIN*16
    const float* X = USE_H ? (const float*)g_h : Xin;

    const int tid = threadIdx.x;
    const int tx = tid & 15;
    const int ty = tid >> 4;

    // Load W: gmem layout [k][i][o] -> smem [i][k][o]
    for (int idx = tid; idx < CIN * 400; idx += 256) {
        int o = idx & 15;
        int r = idx >> 4;          // k*CIN + i
        int i = r % CIN;
        int k = r / CIN;
        Ws[i * 400 + k * 16 + o] = W[idx];
    }
    for (int idx = tid; idx < CIN * 16; idx += 256) Rs[idx] = root[idx];
    const float bv = bias[tx];

    const int ntiles = (N + 63) >> 6;
    for (int tile = blockIdx.x; tile < ntiles; tile += gridDim.x) {
        const int n0 = tile << 6;
        __syncthreads();
        for (int idx = tid; idx < 64 * CIN; idx += 256) {
            int i = idx % CIN;
            int nl = idx / CIN;
            int n = n0 + nl;
            Xs[i * 68 + nl] = (n < N) ? X[(size_t)n * CIN + i] : 0.0f;
        }
        __syncthreads();

        float acc[25][4];
        float rtn[4] = {bv, bv, bv, bv};
        #pragma unroll
        for (int k = 0; k < 25; k++) {
            acc[k][0] = 0.f; acc[k][1] = 0.f; acc[k][2] = 0.f; acc[k][3] = 0.f;
        }
        const int nb = ty * 4;
        #pragma unroll 2
        for (int i = 0; i < CIN; i++) {
            float4 xv = *reinterpret_cast<const float4*>(&Xs[i * 68 + nb]);
            const float* wr = &Ws[i * 400 + tx];
            float rv = Rs[i * 16 + tx];
            rtn[0] += rv * xv.x; rtn[1] += rv * xv.y;
            rtn[2] += rv * xv.z; rtn[3] += rv * xv.w;
            #pragma unroll
            for (int k = 0; k < 25; k++) {
                float w = wr[k * 16];
                acc[k][0] += w * xv.x;
                acc[k][1] += w * xv.y;
                acc[k][2] += w * xv.z;
                acc[k][3] += w * xv.w;
            }
        }
        #pragma unroll
        for (int r = 0; r < 4; r++) {
            int n = n0 + nb + r;
            if (n < N) {
                __half* yo = g_y + (size_t)n * 400 + tx;
                #pragma unroll
                for (int k = 0; k < 25; k++) yo[k * 16] = __float2half_rn(acc[k][r]);
                g_rt[(size_t)n * 16 + tx] = rtn[r];
            }
        }
    }
}

// 2 lanes per edge (q = 8-channel half). 4 corner gathers of 16B fp16 + 2 red.v4 scatters.
__global__ void edge_kernel(const int* __restrict__ src, const int* __restrict__ dst,
                            const float* __restrict__ pseudo, int E, int addDeg) {
    int t = blockIdx.x * blockDim.x + threadIdx.x;
    int e = t >> 1;
    if (e >= E) return;
    int q = t & 1;
    int s = __ldg(src + e);
    int d = __ldg(dst + e);
    float p0 = __ldg(pseudo + 2 * e);
    float p1 = __ldg(pseudo + 2 * e + 1);
    float v0 = p0 * 4.0f, v1 = p1 * 4.0f;
    float fl0 = floorf(v0), fl1 = floorf(v1);
    float f0 = v0 - fl0, f1 = v1 - fl1;
    int i0 = (int)fl0, i1 = (int)fl1;
    int i0b = i0 + 1; if (i0b >= 5) i0b = 0;
    int i1b = i1 + 1; if (i1b >= 5) i1b = 0;
    float g0 = 1.0f - f0, g1 = 1.0f - f1;
    float w00 = g0 * g1, w10 = f0 * g1, w01 = g0 * f1, w11 = f0 * f1;

    // Each corner = 16 halves = 32B = 2 uint4; lane q takes its 16B half.
    const uint4* yb = reinterpret_cast<const uint4*>(g_y + (size_t)s * 400);
    uint4 c00 = __ldg(yb + ((i1  * 5 + i0 ) * 2 + q));
    uint4 c10 = __ldg(yb + ((i1  * 5 + i0b) * 2 + q));
    uint4 c01 = __ldg(yb + ((i1b * 5 + i0 ) * 2 + q));
    uint4 c11 = __ldg(yb + ((i1b * 5 + i0b) * 2 + q));

    float m[8];
    #pragma unroll
    for (int j = 0; j < 4; j++) {
        float2 a = __half22float2(*reinterpret_cast<const __half2*>(((const unsigned*)&c00) + j));
        float2 b = __half22float2(*reinterpret_cast<const __half2*>(((const unsigned*)&c10) + j));
        float2 c = __half22float2(*reinterpret_cast<const __half2*>(((const unsigned*)&c01) + j));
        float2 dd = __half22float2(*reinterpret_cast<const __half2*>(((const unsigned*)&c11) + j));
        m[2 * j + 0] = w00 * a.x + w10 * b.x + w01 * c.x + w11 * dd.x;
        m[2 * j + 1] = w00 * a.y + w10 * b.y + w01 * c.y + w11 * dd.y;
    }

    float* ap = g_agg + (size_t)d * 16 + q * 8;
    red_add_v4(ap,     m[0], m[1], m[2], m[3]);
    red_add_v4(ap + 4, m[4], m[5], m[6], m[7]);
    if (addDeg && q == 0) atomicAdd(g_deg + d, 1.0f);
}

// Pure elementwise epilogue: out = agg/max(deg,1) + rt  (optional ReLU -> g_h)
template<bool RELU_TO_H>
__global__ void node_kernel(float* __restrict__ out, int N) {
    int i = blockIdx.x * blockDim.x + threadIdx.x;
    if (i >= N * 16) return;
    float dg = g_deg[i >> 4];
    dg = dg > 1.0f ? dg : 1.0f;
    float r = g_agg[i] / dg + g_rt[i];
    if (RELU_TO_H) {
        g_h[i] = r > 0.0f ? r : 0.0f;
    } else {
        out[i] = r;
    }
}

extern "C" void kernel_launch(void* const* d_in, const int* in_sizes, int n_in,
                              void* d_out, int out_size) {
    const float* x      = (const float*)d_in[0];
    const int*   ei     = (const int*)  d_in[1];
    const float* pseudo = (const float*)d_in[2];
    const float* W1     = (const float*)d_in[3];
    const float* root1  = (const float*)d_in[4];
    const float* b1     = (const float*)d_in[5];
    const float* W2     = (const float*)d_in[6];
    const float* root2  = (const float*)d_in[7];
    const float* b2     = (const float*)d_in[8];
    float* out = (float*)d_out;

    int N = in_sizes[0] / 64;
    int E = in_sizes[1] / 2;
    if (N > NCAP) N = NCAP;
    const int* src = ei;
    const int* dst = ei + E;

    const int smem1 = (64 * 400 + 64 * 68 + 64 * 16) * 4;   // 123904 B
    const int smem2 = (16 * 400 + 16 * 68 + 16 * 16) * 4;   // 30976 B
    cudaFuncSetAttribute((const void*)y_kernel<64, false>,
                         cudaFuncAttributeMaxDynamicSharedMemorySize, smem1);

    int nodeGrid = (N * 16 + 255) / 256;
    int edgeGrid = (E * 2 + 255) / 256;
    int ntiles = (N + 63) / 64;
    int yGrid = ntiles < 592 ? ntiles : 592;

    // ---- Layer 1 ----
    zero_kernel<<<nodeGrid, 256>>>(N * 16, N);
    y_kernel<64, false><<<yGrid, 256, smem1>>>(x, W1, root1, b1, N);
    edge_kernel<<<edgeGrid, 256>>>(src, dst, pseudo, E, 1);
    node_kernel<true><<<nodeGrid, 256>>>(nullptr, N);

    // ---- Layer 2 ----
    zero_kernel<<<nodeGrid, 256>>>(N * 16, 0);
    y_kernel<16, true><<<yGrid, 256, smem2>>>(nullptr, W2, root2, b2, N);
    edge_kernel<<<edgeGrid, 256>>>(src, dst, pseudo, E, 0);
    node_kernel<false><<<nodeGrid, 256>>>(out, N);
}

// round 4
// speedup vs baseline: 1.5272x; 1.3200x over previous
#include <cuda_runtime.h>
#include <cuda_fp16.h>
#include <cuda_bf16.h>
#include <math.h>
#include <stdint.h>

// Problem constants: N=100000, E=1600000, Cin=64, H=16, Cout=16, K=5
#define NCAP 100096   // multiple of 128

// Scratch (allocation-free contract).
__device__ __half g_y[(size_t)NCAP * 400];     // per-kernel products, fp16
__device__ float  g_agg[(size_t)NCAP * 16];    // per-layer aggregation
__device__ float  g_deg[NCAP];                 // in-degree
__device__ float  g_h[(size_t)NCAP * 16];      // layer-1 output (post ReLU)
__device__ float  g_rt[(size_t)NCAP * 16];     // x @ root + bias
// B in HMMA-fragment layout: [term(2)][ntile(52)][kstep(4)][lane(32)][reg(2)] u32
#define BFRAG_U32 (2 * 52 * 4 * 64)
__device__ uint32_t g_B1[BFRAG_U32];
__device__ uint32_t g_B2[BFRAG_U32];

__device__ __forceinline__ void red_add_v4(float* a, float x, float y, float z, float w) {
    asm volatile("red.global.add.v4.f32 [%0], {%1, %2, %3, %4};"
                 :: "l"(a), "f"(x), "f"(y), "f"(z), "f"(w) : "memory");
}

// mma.sync m16n8k16 bf16 (sm_80+ — no 'a'-gated features)
__device__ __forceinline__ void mma_bf16(float* c, uint32_t a0, uint32_t a1,
                                         uint32_t a2, uint32_t a3,
                                         uint32_t b0, uint32_t b1) {
    asm volatile("mma.sync.aligned.m16n8k16.row.col.f32.bf16.bf16.f32 "
                 "{%0,%1,%2,%3}, {%4,%5,%6,%7}, {%8,%9}, {%0,%1,%2,%3};"
                 : "+f"(c[0]), "+f"(c[1]), "+f"(c[2]), "+f"(c[3])
                 : "r"(a0), "r"(a1), "r"(a2), "r"(a3), "r"(b0), "r"(b1));
}

__global__ void zero_kernel(int nAgg, int nDeg) {
    int i = blockIdx.x * blockDim.x + threadIdx.x;
    if (i < nAgg) g_agg[i] = 0.0f;
    if (i < nDeg) g_deg[i] = 0.0f;
}

// Build B fragments. Logical B[n=0..415][k=0..63]: n<400 -> W[(kk*CIN+k)*16+o]
// (kk=n>>4, o=n&15); n>=400 -> root[k*16 + (n-400)]. hi/lo bf16 split.
// Fragment (m16n8k16 col-major B): reg0 holds k = tig*2,+1 ; reg1 k = tig*2+8,+9 ;
// n = ntile*8 + (lane>>2); tig = lane&3.  Packed u32: low half = lower-k element.
template<int CIN>
__global__ void prepB_kernel(const float* __restrict__ W, const float* __restrict__ root,
                             uint32_t* __restrict__ Bg) {
    int idx = blockIdx.x * blockDim.x + threadIdx.x;
    if (idx >= BFRAG_U32) return;
    int term = idx / (52 * 4 * 64);
    int r = idx % (52 * 4 * 64);
    int ntile = r / 256;
    int r2 = r % 256;
    int kstep = r2 / 64;
    int q = r2 % 64;
    int lane = q >> 1;
    int reg = q & 1;
    int n = ntile * 8 + (lane >> 2);
    int k0 = kstep * 16 + (lane & 3) * 2 + reg * 8;

    float v[2];
    #pragma unroll
    for (int j = 0; j < 2; j++) {
        int k = k0 + j;
        float val = 0.0f;
        if (k < CIN) {
            if (n < 400) {
                int kk = n >> 4, o = n & 15;
                val = W[(kk * CIN + k) * 16 + o];
            } else {
                val = root[k * 16 + (n - 400)];
            }
        }
        v[j] = val;
    }
    uint32_t out;
    if (term == 0) {
        __nv_bfloat16 b0 = __float2bfloat16(v[0]);
        __nv_bfloat16 b1 = __float2bfloat16(v[1]);
        out = (uint32_t)__bfloat16_as_ushort(b0) | ((uint32_t)__bfloat16_as_ushort(b1) << 16);
    } else {
        __nv_bfloat16 h0 = __float2bfloat16(v[0]);
        __nv_bfloat16 h1 = __float2bfloat16(v[1]);
        __nv_bfloat16 l0 = __float2bfloat16(v[0] - __bfloat162float(h0));
        __nv_bfloat16 l1 = __float2bfloat16(v[1] - __bfloat162float(h1));
        out = (uint32_t)__bfloat16_as_ushort(l0) | ((uint32_t)__bfloat16_as_ushort(l1) << 16);
    }
    Bg[idx] = out;
}

// HMMA GEMM: per CTA M=128 nodes, N=416 (400 y cols fp16 + 16 rt cols fp32+bias), K=CIN.
// 4 warps x 2 m16 tiles. A staged hi/lo in smem, fragments kept in regs.
template<bool USE_H, int KSTEPS>
__global__ void __launch_bounds__(128) gemm_kernel(const float* __restrict__ Xin,
                                                   const uint32_t* __restrict__ Bg,
                                                   const float* __restrict__ bias, int N) {
    __shared__ uint32_t Asm[2][128][33];  // [term][row][k-pair u32], padded
    const int tid = threadIdx.x;
    const int wid = tid >> 5;
    const int lane = tid & 31;
    const int gID = lane >> 2;
    const int tig = lane & 3;
    const int n0 = blockIdx.x * 128;

    // Load & convert this thread's node row into smem (hi/lo bf16 pairs).
    {
        const int n = n0 + tid;
        float xv[64];
        if (USE_H) {
            #pragma unroll
            for (int c = 0; c < 16; c++) xv[c] = (n < N) ? g_h[(size_t)n * 16 + c] : 0.0f;
            #pragma unroll
            for (int c = 16; c < 64; c++) xv[c] = 0.0f;
        } else {
            const float4* xr = reinterpret_cast<const float4*>(Xin + (size_t)n * 64);
            #pragma unroll
            for (int c = 0; c < 16; c++) {
                float4 f = (n < N) ? __ldg(xr + c) : make_float4(0.f, 0.f, 0.f, 0.f);
                xv[4 * c] = f.x; xv[4 * c + 1] = f.y; xv[4 * c + 2] = f.z; xv[4 * c + 3] = f.w;
            }
        }
        #pragma unroll
        for (int j = 0; j < 32; j++) {
            __nv_bfloat16 h0 = __float2bfloat16(xv[2 * j]);
            __nv_bfloat16 h1 = __float2bfloat16(xv[2 * j + 1]);
            Asm[0][tid][j] = (uint32_t)__bfloat16_as_ushort(h0) |
                             ((uint32_t)__bfloat16_as_ushort(h1) << 16);
            __nv_bfloat16 l0 = __float2bfloat16(xv[2 * j] - __bfloat162float(h0));
            __nv_bfloat16 l1 = __float2bfloat16(xv[2 * j + 1] - __bfloat162float(h1));
            Asm[1][tid][j] = (uint32_t)__bfloat16_as_ushort(l0) |
                             ((uint32_t)__bfloat16_as_ushort(l1) << 16);
        }
    }
    __syncthreads();

    // A fragments: [term][mtile][kstep][4 regs]
    uint32_t a[2][2][KSTEPS][4];
    #pragma unroll
    for (int term = 0; term < 2; term++)
        #pragma unroll
        for (int mt = 0; mt < 2; mt++) {
            int r0 = wid * 32 + mt * 16 + gID;
            #pragma unroll
            for (int ks = 0; ks < KSTEPS; ks++) {
                a[term][mt][ks][0] = Asm[term][r0][ks * 8 + tig];
                a[term][mt][ks][1] = Asm[term][r0 + 8][ks * 8 + tig];
                a[term][mt][ks][2] = Asm[term][r0][ks * 8 + tig + 4];
                a[term][mt][ks][3] = Asm[term][r0 + 8][ks * 8 + tig + 4];
            }
        }

    #pragma unroll 1
    for (int chunk = 0; chunk < 13; chunk++) {
        float c[2][4][4];
        #pragma unroll
        for (int mt = 0; mt < 2; mt++)
            #pragma unroll
            for (int nt = 0; nt < 4; nt++)
                #pragma unroll
                for (int r = 0; r < 4; r++) c[mt][nt][r] = 0.0f;

        #pragma unroll
        for (int ks = 0; ks < KSTEPS; ks++) {
            #pragma unroll
            for (int nt = 0; nt < 4; nt++) {
                int ntg = chunk * 4 + nt;
                const uint2* bph = reinterpret_cast<const uint2*>(
                    Bg + (size_t)(ntg * 4 + ks) * 64) + lane;
                const uint2* bpl = reinterpret_cast<const uint2*>(
                    Bg + (size_t)((52 + ntg) * 4 + ks) * 64) + lane;
                uint2 bh = __ldg(bph);
                uint2 bl = __ldg(bpl);
                #pragma unroll
                for (int mt = 0; mt < 2; mt++) {
                    mma_bf16(c[mt][nt], a[0][mt][ks][0], a[0][mt][ks][1],
                             a[0][mt][ks][2], a[0][mt][ks][3], bh.x, bh.y);
                    mma_bf16(c[mt][nt], a[1][mt][ks][0], a[1][mt][ks][1],
                             a[1][mt][ks][2], a[1][mt][ks][3], bh.x, bh.y);
                    mma_bf16(c[mt][nt], a[0][mt][ks][0], a[0][mt][ks][1],
                             a[0][mt][ks][2], a[0][mt][ks][3], bl.x, bl.y);
                }
            }
        }

        // Epilogue for this chunk.
        #pragma unroll
        for (int mt = 0; mt < 2; mt++)
            #pragma unroll
            for (int nt = 0; nt < 4; nt++) {
                int col = chunk * 32 + nt * 8 + tig * 2;
                int row0 = n0 + wid * 32 + mt * 16 + gID;
                int row1 = row0 + 8;
                float* cc = c[mt][nt];
                if (col < 400) {
                    if (row0 < N)
                        *reinterpret_cast<__half2*>(g_y + (size_t)row0 * 400 + col) =
                            __floats2half2_rn(cc[0], cc[1]);
                    if (row1 < N)
                        *reinterpret_cast<__half2*>(g_y + (size_t)row1 * 400 + col) =
                            __floats2half2_rn(cc[2], cc[3]);
                } else {
                    int o = col - 400;
                    float bv0 = __ldg(bias + o), bv1 = __ldg(bias + o + 1);
                    if (row0 < N) {
                        g_rt[(size_t)row0 * 16 + o] = cc[0] + bv0;
                        g_rt[(size_t)row0 * 16 + o + 1] = cc[1] + bv1;
                    }
                    if (row1 < N) {
                        g_rt[(size_t)row1 * 16 + o] = cc[2] + bv0;
                        g_rt[(size_t)row1 * 16 + o + 1] = cc[3] + bv1;
                    }
                }
            }
    }
}

// ---------------- edge + node kernels (round-2 proven) ----------------
__global__ void edge_kernel(const int* __restrict__ src, const int* __restrict__ dst,
                            const float* __restrict__ pseudo, int E, int addDeg) {
    int t = blockIdx.x * blockDim.x + threadIdx.x;
    int e = t >> 1;
    if (e >= E) return;
    int q = t & 1;
    int s = __ldg(src + e);
    int d = __ldg(dst + e);
    float p0 = __ldg(pseudo + 2 * e);
    float p1 = __ldg(pseudo + 2 * e + 1);
    float v0 = p0 * 4.0f, v1 = p1 * 4.0f;
    float fl0 = floorf(v0), fl1 = floorf(v1);
    float f0 = v0 - fl0, f1 = v1 - fl1;
    int i0 = (int)fl0, i1 = (int)fl1;
    int i0b = i0 + 1; if (i0b >= 5) i0b = 0;
    int i1b = i1 + 1; if (i1b >= 5) i1b = 0;
    float g0 = 1.0f - f0, g1 = 1.0f - f1;
    float w00 = g0 * g1, w10 = f0 * g1, w01 = g0 * f1, w11 = f0 * f1;

    const uint4* yb = reinterpret_cast<const uint4*>(g_y + (size_t)s * 400);
    uint4 c00 = __ldg(yb + ((i1  * 5 + i0 ) * 2 + q));
    uint4 c10 = __ldg(yb + ((i1  * 5 + i0b) * 2 + q));
    uint4 c01 = __ldg(yb + ((i1b * 5 + i0 ) * 2 + q));
    uint4 c11 = __ldg(yb + ((i1b * 5 + i0b) * 2 + q));

    float m[8];
    #pragma unroll
    for (int j = 0; j < 4; j++) {
        float2 a = __half22float2(*reinterpret_cast<const __half2*>(((const unsigned*)&c00) + j));
        float2 b = __half22float2(*reinterpret_cast<const __half2*>(((const unsigned*)&c10) + j));
        float2 c = __half22float2(*reinterpret_cast<const __half2*>(((const unsigned*)&c01) + j));
        float2 dd = __half22float2(*reinterpret_cast<const __half2*>(((const unsigned*)&c11) + j));
        m[2 * j + 0] = w00 * a.x + w10 * b.x + w01 * c.x + w11 * dd.x;
        m[2 * j + 1] = w00 * a.y + w10 * b.y + w01 * c.y + w11 * dd.y;
    }

    float* ap = g_agg + (size_t)d * 16 + q * 8;
    red_add_v4(ap,     m[0], m[1], m[2], m[3]);
    red_add_v4(ap + 4, m[4], m[5], m[6], m[7]);
    if (addDeg && q == 0) atomicAdd(g_deg + d, 1.0f);
}

template<bool RELU_TO_H>
__global__ void node_kernel(float* __restrict__ out, int N) {
    int i = blockIdx.x * blockDim.x + threadIdx.x;
    if (i >= N * 16) return;
    float dg = g_deg[i >> 4];
    dg = dg > 1.0f ? dg : 1.0f;
    float r = g_agg[i] / dg + g_rt[i];
    if (RELU_TO_H) {
        g_h[i] = r > 0.0f ? r : 0.0f;
    } else {
        out[i] = r;
    }
}

extern "C" void kernel_launch(void* const* d_in, const int* in_sizes, int n_in,
                              void* d_out, int out_size) {
    const float* x      = (const float*)d_in[0];
    const int*   ei     = (const int*)  d_in[1];
    const float* pseudo = (const float*)d_in[2];
    const float* W1     = (const float*)d_in[3];
    const float* root1  = (const float*)d_in[4];
    const float* b1     = (const float*)d_in[5];
    const float* W2     = (const float*)d_in[6];
    const float* root2  = (const float*)d_in[7];
    const float* b2     = (const float*)d_in[8];
    float* out = (float*)d_out;

    int N = in_sizes[0] / 64;
    int E = in_sizes[1] / 2;
    if (N > NCAP) N = NCAP;
    const int* src = ei;
    const int* dst = ei + E;

    static uint32_t* B1p = nullptr;
    static uint32_t* B2p = nullptr;
    if (!B1p) {
        cudaGetSymbolAddress((void**)&B1p, g_B1);
        cudaGetSymbolAddress((void**)&B2p, g_B2);
    }

    int nodeGrid = (N * 16 + 255) / 256;
    int edgeGrid = (E * 2 + 255) / 256;
    int gemmGrid = (N + 127) / 128;
    int prepGrid = (BFRAG_U32 + 255) / 256;

    // ---- Layer 1 ----
    prepB_kernel<64><<<prepGrid, 256>>>(W1, root1, B1p);
    prepB_kernel<16><<<prepGrid, 256>>>(W2, root2, B2p);
    zero_kernel<<<nodeGrid, 256>>>(N * 16, N);
    gemm_kernel<false, 4><<<gemmGrid, 128>>>(x, B1p, b1, N);
    edge_kernel<<<edgeGrid, 256>>>(src, dst, pseudo, E, 1);
    node_kernel<true><<<nodeGrid, 256>>>(nullptr, N);

    // ---- Layer 2 ----
    zero_kernel<<<nodeGrid, 256>>>(N * 16, 0);
    gemm_kernel<true, 1><<<gemmGrid, 128>>>(nullptr, B2p, b2, N);
    edge_kernel<<<edgeGrid, 256>>>(src, dst, pseudo, E, 0);
    node_kernel<false><<<nodeGrid, 256>>>(out, N);
}

// round 5
// speedup vs baseline: 1.9804x; 1.2968x over previous
#include <cuda_runtime.h>
#include <cuda_fp16.h>
#include <cuda_bf16.h>
#include <math.h>
#include <stdint.h>

// Problem constants: N=100000, E=1600000, Cin=64, H=16, Cout=16, K=5
#define NCAP 100096   // multiple of 128

// Scratch (allocation-free contract).
__device__ __half g_y[(size_t)NCAP * 400];     // per-kernel products, fp16
__device__ float  g_agg[(size_t)NCAP * 16];    // per-layer aggregation
__device__ float  g_deg[NCAP];                 // in-degree
__device__ float  g_h[(size_t)NCAP * 16];      // layer-1 output (post ReLU)
__device__ float  g_rt[(size_t)NCAP * 16];     // x @ root + bias
// B in tf32 fragment layout: [ntile(52)][kstep][lane(32)*2] u32
__device__ uint32_t g_B1[52 * 8 * 64];
__device__ uint32_t g_B2[52 * 2 * 64];

__device__ __forceinline__ void red_add_v4(float* a, float x, float y, float z, float w) {
    asm volatile("red.global.add.v4.f32 [%0], {%1, %2, %3, %4};"
                 :: "l"(a), "f"(x), "f"(y), "f"(z), "f"(w) : "memory");
}
__device__ __forceinline__ uint32_t f2tf32(float f) {
    uint32_t o;
    asm("cvt.rna.tf32.f32 %0, %1;" : "=r"(o) : "f"(f));
    return o;
}
__device__ __forceinline__ void mma_tf32(float* c, const uint32_t* a, uint32_t b0, uint32_t b1) {
    asm volatile("mma.sync.aligned.m16n8k8.row.col.f32.tf32.tf32.f32 "
                 "{%0,%1,%2,%3}, {%4,%5,%6,%7}, {%8,%9}, {%0,%1,%2,%3};"
                 : "+f"(c[0]), "+f"(c[1]), "+f"(c[2]), "+f"(c[3])
                 : "r"(a[0]), "r"(a[1]), "r"(a[2]), "r"(a[3]), "r"(b0), "r"(b1));
}
__device__ __forceinline__ void cp_async16(uint32_t saddr, const void* g) {
    asm volatile("cp.async.cg.shared.global [%0], [%1], 16;" :: "r"(saddr), "l"(g));
}
#define CP_COMMIT() asm volatile("cp.async.commit_group;" ::: "memory")
#define CP_WAIT1()  asm volatile("cp.async.wait_group 1;" ::: "memory")
__device__ __forceinline__ uint32_t smem_u32(const void* p) {
    uint32_t a;
    asm("{ .reg .u64 t; cvta.to.shared.u64 t, %1; cvt.u32.u64 %0, t; }" : "=r"(a) : "l"(p));
    return a;
}

__global__ void zero_kernel(int nAgg, int nDeg) {
    int i = blockIdx.x * blockDim.x + threadIdx.x;
    if (i < nAgg) g_agg[i] = 0.0f;
    if (i < nDeg) g_deg[i] = 0.0f;
}

// Build tf32 B fragments. Logical B[n=0..415][k]: n<400 -> W[(kk*CIN+k)*16+o]
// (kk=n>>4, o=n&15); n>=400 -> root[k*16+(n-400)].
// m16n8k8 col-B frag: n = ntile*8 + (lane>>2); k = ks*8 + (lane&3) + reg*4.
template<int CIN, int KSTEPS>
__global__ void prepB_kernel(const float* __restrict__ W, const float* __restrict__ root,
                             uint32_t* __restrict__ Bg) {
    int idx = blockIdx.x * blockDim.x + threadIdx.x;
    if (idx >= 52 * KSTEPS * 64) return;
    int ntile = idx / (KSTEPS * 64);
    int rem = idx % (KSTEPS * 64);
    int ks = rem / 64;
    int q = rem % 64;
    int lane = q >> 1;
    int reg = q & 1;
    int n = ntile * 8 + (lane >> 2);
    int k = ks * 8 + (lane & 3) + reg * 4;
    float v = 0.0f;
    if (k < CIN) {
        if (n < 400) {
            int kk = n >> 4, o = n & 15;
            v = W[(kk * CIN + k) * 16 + o];
        } else {
            v = root[k * 16 + (n - 400)];
        }
    }
    Bg[idx] = f2tf32(v);
}

// HMMA tf32 GEMM: per CTA M=128 nodes, N=416 (400 y cols fp16 + 16 rt cols fp32+bias).
// 4 warps x 2 m16 tiles; A tf32 in smem -> regs; B cp.async double-buffered per 32-col chunk.
template<bool USE_H, int KSTEPS>
__global__ void __launch_bounds__(128) gemm_kernel(const float* __restrict__ Xin,
                                                   const uint32_t* __restrict__ Bg,
                                                   const float* __restrict__ bias, int N) {
    constexpr int KC = KSTEPS * 8;          // real K
    constexpr int AP = KC + 4;              // A row pitch (u32)
    constexpr int CHUNK_U32 = 4 * KSTEPS * 64;
    extern __shared__ uint32_t sm[];
    uint32_t* Asm = sm;                      // [128][AP]
    uint32_t* Bbuf = sm + 128 * AP;          // [2][CHUNK_U32]
    const uint32_t bbase = smem_u32(Bbuf);

    const int tid = threadIdx.x;
    const int wid = tid >> 5;
    const int lane = tid & 31;
    const int gID = lane >> 2;
    const int tig = lane & 3;
    const int n0 = blockIdx.x * 128;

    // Prefetch chunk 0 B while converting A.
    {
        constexpr int PT = CHUNK_U32 / (128 * 4);  // 16B loads per thread
        #pragma unroll
        for (int i = 0; i < PT; i++)
            cp_async16(bbase + (tid + i * 128) * 16, (const char*)Bg + (tid + i * 128) * 16);
        CP_COMMIT();
    }

    // Convert this thread's node row to tf32 in smem.
    {
        const int n = n0 + tid;
        const float4* xr = USE_H ? reinterpret_cast<const float4*>(g_h + (size_t)n * 16)
                                 : reinterpret_cast<const float4*>(Xin + (size_t)n * 64);
        #pragma unroll
        for (int c = 0; c < KC / 4; c++) {
            float4 f = (n < N) ? __ldg(xr + c) : make_float4(0.f, 0.f, 0.f, 0.f);
            Asm[tid * AP + 4 * c]     = f2tf32(f.x);
            Asm[tid * AP + 4 * c + 1] = f2tf32(f.y);
            Asm[tid * AP + 4 * c + 2] = f2tf32(f.z);
            Asm[tid * AP + 4 * c + 3] = f2tf32(f.w);
        }
    }
    __syncthreads();

    // A fragments: [mtile][kstep][4]
    uint32_t a[2][KSTEPS][4];
    #pragma unroll
    for (int mt = 0; mt < 2; mt++) {
        int r0 = wid * 32 + mt * 16 + gID;
        #pragma unroll
        for (int ks = 0; ks < KSTEPS; ks++) {
            a[mt][ks][0] = Asm[r0 * AP + ks * 8 + tig];
            a[mt][ks][1] = Asm[(r0 + 8) * AP + ks * 8 + tig];
            a[mt][ks][2] = Asm[r0 * AP + ks * 8 + tig + 4];
            a[mt][ks][3] = Asm[(r0 + 8) * AP + ks * 8 + tig + 4];
        }
    }

    #pragma unroll 1
    for (int chunk = 0; chunk < 13; chunk++) {
        // Prefetch next chunk into the other buffer.
        if (chunk + 1 < 13) {
            constexpr int PT = CHUNK_U32 / (128 * 4);
            uint32_t dst = bbase + ((chunk + 1) & 1) * (CHUNK_U32 * 4);
            const char* src = (const char*)(Bg + (size_t)(chunk + 1) * CHUNK_U32);
            #pragma unroll
            for (int i = 0; i < PT; i++)
                cp_async16(dst + (tid + i * 128) * 16, src + (tid + i * 128) * 16);
        }
        CP_COMMIT();
        CP_WAIT1();
        __syncthreads();

        const uint32_t* bb = Bbuf + (chunk & 1) * CHUNK_U32;
        float c[2][4][4];
        #pragma unroll
        for (int mt = 0; mt < 2; mt++)
            #pragma unroll
            for (int nt = 0; nt < 4; nt++)
                #pragma unroll
                for (int r = 0; r < 4; r++) c[mt][nt][r] = 0.0f;

        #pragma unroll
        for (int ks = 0; ks < KSTEPS; ks++)
            #pragma unroll
            for (int nt = 0; nt < 4; nt++) {
                uint2 b = *reinterpret_cast<const uint2*>(bb + (nt * KSTEPS + ks) * 64 + lane * 2);
                mma_tf32(c[0][nt], a[0][ks], b.x, b.y);
                mma_tf32(c[1][nt], a[1][ks], b.x, b.y);
            }
        __syncthreads();  // all warps done with this buffer before it is re-filled

        // Epilogue for this chunk.
        #pragma unroll
        for (int mt = 0; mt < 2; mt++)
            #pragma unroll
            for (int nt = 0; nt < 4; nt++) {
                int col = chunk * 32 + nt * 8 + tig * 2;
                int row0 = n0 + wid * 32 + mt * 16 + gID;
                int row1 = row0 + 8;
                float* cc = c[mt][nt];
                if (col < 400) {
                    if (row0 < N)
                        *reinterpret_cast<__half2*>(g_y + (size_t)row0 * 400 + col) =
                            __floats2half2_rn(cc[0], cc[1]);
                    if (row1 < N)
                        *reinterpret_cast<__half2*>(g_y + (size_t)row1 * 400 + col) =
                            __floats2half2_rn(cc[2], cc[3]);
                } else {
                    int o = col - 400;
                    float bv0 = __ldg(bias + o), bv1 = __ldg(bias + o + 1);
                    if (row0 < N) {
                        g_rt[(size_t)row0 * 16 + o] = cc[0] + bv0;
                        g_rt[(size_t)row0 * 16 + o + 1] = cc[1] + bv1;
                    }
                    if (row1 < N) {
                        g_rt[(size_t)row1 * 16 + o] = cc[2] + bv0;
                        g_rt[(size_t)row1 * 16 + o + 1] = cc[3] + bv1;
                    }
                }
            }
    }
}

// ---------------- edge + node kernels (round-2 proven) ----------------
__global__ void edge_kernel(const int* __restrict__ src, const int* __restrict__ dst,
                            const float* __restrict__ pseudo, int E, int addDeg) {
    int t = blockIdx.x * blockDim.x + threadIdx.x;
    int e = t >> 1;
    if (e >= E) return;
    int q = t & 1;
    int s = __ldg(src + e);
    int d = __ldg(dst + e);
    float p0 = __ldg(pseudo + 2 * e);
    float p1 = __ldg(pseudo + 2 * e + 1);
    float v0 = p0 * 4.0f, v1 = p1 * 4.0f;
    float fl0 = floorf(v0), fl1 = floorf(v1);
    float f0 = v0 - fl0, f1 = v1 - fl1;
    int i0 = (int)fl0, i1 = (int)fl1;
    int i0b = i0 + 1; if (i0b >= 5) i0b = 0;
    int i1b = i1 + 1; if (i1b >= 5) i1b = 0;
    float g0 = 1.0f - f0, g1 = 1.0f - f1;
    float w00 = g0 * g1, w10 = f0 * g1, w01 = g0 * f1, w11 = f0 * f1;

    const uint4* yb = reinterpret_cast<const uint4*>(g_y + (size_t)s * 400);
    uint4 c00 = __ldg(yb + ((i1  * 5 + i0 ) * 2 + q));
    uint4 c10 = __ldg(yb + ((i1  * 5 + i0b) * 2 + q));
    uint4 c01 = __ldg(yb + ((i1b * 5 + i0 ) * 2 + q));
    uint4 c11 = __ldg(yb + ((i1b * 5 + i0b) * 2 + q));

    float m[8];
    #pragma unroll
    for (int j = 0; j < 4; j++) {
        float2 a = __half22float2(*reinterpret_cast<const __half2*>(((const unsigned*)&c00) + j));
        float2 b = __half22float2(*reinterpret_cast<const __half2*>(((const unsigned*)&c10) + j));
        float2 c = __half22float2(*reinterpret_cast<const __half2*>(((const unsigned*)&c01) + j));
        float2 dd = __half22float2(*reinterpret_cast<const __half2*>(((const unsigned*)&c11) + j));
        m[2 * j + 0] = w00 * a.x + w10 * b.x + w01 * c.x + w11 * dd.x;
        m[2 * j + 1] = w00 * a.y + w10 * b.y + w01 * c.y + w11 * dd.y;
    }

    float* ap = g_agg + (size_t)d * 16 + q * 8;
    red_add_v4(ap,     m[0], m[1], m[2], m[3]);
    red_add_v4(ap + 4, m[4], m[5], m[6], m[7]);
    if (addDeg && q == 0) atomicAdd(g_deg + d, 1.0f);
}

template<bool RELU_TO_H>
__global__ void node_kernel(float* __restrict__ out, int N) {
    int i = blockIdx.x * blockDim.x + threadIdx.x;
    if (i >= N * 16) return;
    float dg = g_deg[i >> 4];
    dg = dg > 1.0f ? dg : 1.0f;
    float r = g_agg[i] / dg + g_rt[i];
    if (RELU_TO_H) {
        g_h[i] = r > 0.0f ? r : 0.0f;
    } else {
        out[i] = r;
    }
}

extern "C" void kernel_launch(void* const* d_in, const int* in_sizes, int n_in,
                              void* d_out, int out_size) {
    const float* x      = (const float*)d_in[0];
    const int*   ei     = (const int*)  d_in[1];
    const float* pseudo = (const float*)d_in[2];
    const float* W1     = (const float*)d_in[3];
    const float* root1  = (const float*)d_in[4];
    const float* b1     = (const float*)d_in[5];
    const float* W2     = (const float*)d_in[6];
    const float* root2  = (const float*)d_in[7];
    const float* b2     = (const float*)d_in[8];
    float* out = (float*)d_out;

    int N = in_sizes[0] / 64;
    int E = in_sizes[1] / 2;
    if (N > NCAP) N = NCAP;
    const int* src = ei;
    const int* dst = ei + E;

    // smem: layer1 = 128*68*4 + 2*2048*4 = 34816+16384 = 51200; layer2 = 128*20*4 + 2*512*4 = 14336
    const int smem1 = 51200, smem2 = 14336;
    static uint32_t *B1p = nullptr, *B2p = nullptr;
    if (!B1p) {
        cudaGetSymbolAddress((void**)&B1p, g_B1);
        cudaGetSymbolAddress((void**)&B2p, g_B2);
        cudaFuncSetAttribute((const void*)gemm_kernel<false, 8>,
                             cudaFuncAttributeMaxDynamicSharedMemorySize, smem1);
        cudaFuncSetAttribute((const void*)gemm_kernel<true, 2>,
                             cudaFuncAttributeMaxDynamicSharedMemorySize, smem2);
    }

    int nodeGrid = (N * 16 + 255) / 256;
    int edgeGrid = (E * 2 + 255) / 256;
    int gemmGrid = (N + 127) / 128;

    // ---- Layer 1 ----
    prepB_kernel<64, 8><<<(52 * 8 * 64 + 255) / 256, 256>>>(W1, root1, B1p);
    prepB_kernel<16, 2><<<(52 * 2 * 64 + 255) / 256, 256>>>(W2, root2, B2p);
    zero_kernel<<<nodeGrid, 256>>>(N * 16, N);
    gemm_kernel<false, 8><<<gemmGrid, 128, smem1>>>(x, B1p, b1, N);
    edge_kernel<<<edgeGrid, 256>>>(src, dst, pseudo, E, 1);
    node_kernel<true><<<nodeGrid, 256>>>(nullptr, N);

    // ---- Layer 2 ----
    zero_kernel<<<nodeGrid, 256>>>(N * 16, 0);
    gemm_kernel<true, 2><<<gemmGrid, 128, smem2>>>(nullptr, B2p, b2, N);
    edge_kernel<<<edgeGrid, 256>>>(src, dst, pseudo, E, 0);
    node_kernel<false><<<nodeGrid, 256>>>(out, N);
}

// round 7
// speedup vs baseline: 2.1211x; 1.0710x over previous
#include <cuda_runtime.h>
#include <cuda_fp16.h>
#include <math.h>
#include <stdint.h>

// Problem constants: N=100000, E=1600000, Cin=64, H=16, Cout=16, K=5
#define NCAP 100096   // multiple of 128

// Scratch (allocation-free contract).
__device__ __half g_y[(size_t)NCAP * 400];     // per-kernel products, fp16
__device__ float  g_agg[(size_t)NCAP * 16];    // per-layer aggregation
__device__ float  g_deg[NCAP];                 // in-degree
__device__ float  g_rt[(size_t)NCAP * 16];     // x @ root + bias (per layer)
// B in tf32 fragment layout: [ntile(52)][kstep][lane(32)*2] u32
__device__ uint32_t g_B1[52 * 8 * 64];
__device__ uint32_t g_B2[52 * 2 * 64];

__device__ __forceinline__ void red_add_v4(float* a, float x, float y, float z, float w) {
    asm volatile("red.global.add.v4.f32 [%0], {%1, %2, %3, %4};"
                 :: "l"(a), "f"(x), "f"(y), "f"(z), "f"(w) : "memory");
}
__device__ __forceinline__ uint32_t f2tf32(float f) {
    uint32_t o;
    asm("cvt.rna.tf32.f32 %0, %1;" : "=r"(o) : "f"(f));
    return o;
}
__device__ __forceinline__ void mma_tf32(float* c, const uint32_t* a, uint32_t b0, uint32_t b1) {
    asm volatile("mma.sync.aligned.m16n8k8.row.col.f32.tf32.tf32.f32 "
                 "{%0,%1,%2,%3}, {%4,%5,%6,%7}, {%8,%9}, {%0,%1,%2,%3};"
                 : "+f"(c[0]), "+f"(c[1]), "+f"(c[2]), "+f"(c[3])
                 : "r"(a[0]), "r"(a[1]), "r"(a[2]), "r"(a[3]), "r"(b0), "r"(b1));
}
__device__ __forceinline__ void cp_async16(uint32_t saddr, const void* g) {
    asm volatile("cp.async.cg.shared.global [%0], [%1], 16;" :: "r"(saddr), "l"(g));
}
#define CP_COMMIT() asm volatile("cp.async.commit_group;" ::: "memory")
#define CP_WAIT1()  asm volatile("cp.async.wait_group 1;" ::: "memory")
__device__ __forceinline__ uint32_t smem_u32(const void* p) {
    uint32_t a;
    asm("{ .reg .u64 t; cvta.to.shared.u64 t, %1; cvt.u32.u64 %0, t; }" : "=r"(a) : "l"(p));
    return a;
}

// Build tf32 B fragments. Logical B[n=0..415][k]: n<400 -> W[(kk*CIN+k)*16+o]
// (kk=n>>4, o=n&15); n>=400 -> root[k*16+(n-400)].
// m16n8k8 col-B frag: n = ntile*8 + (lane>>2); k = ks*8 + (lane&3) + reg*4.
template<int CIN, int KSTEPS>
__global__ void prepB_kernel(const float* __restrict__ W, const float* __restrict__ root,
                             uint32_t* __restrict__ Bg) {
    int idx = blockIdx.x * blockDim.x + threadIdx.x;
    if (idx >= 52 * KSTEPS * 64) return;
    int ntile = idx / (KSTEPS * 64);
    int rem = idx % (KSTEPS * 64);
    int ks = rem / 64;
    int q = rem % 64;
    int lane = q >> 1;
    int reg = q & 1;
    int n = ntile * 8 + (lane >> 2);
    int k = ks * 8 + (lane & 3) + reg * 4;
    float v = 0.0f;
    if (k < CIN) {
        if (n < 400) {
            int kk = n >> 4, o = n & 15;
            v = W[(kk * CIN + k) * 16 + o];
        } else {
            v = root[k * 16 + (n - 400)];
        }
    }
    Bg[idx] = f2tf32(v);
}

// HMMA tf32 GEMM + fusions. Per CTA: M=128 nodes, N=416 (400 y cols fp16 + 16 rt cols fp32+bias).
// LAYER=1: A = Xin; also zero g_agg + g_deg for its rows (before edge pass 1).
// LAYER=2: A = relu(agg/max(deg,1) + rt) computed inline; then re-zero g_agg for layer 2.
template<int LAYER, int KSTEPS>
__global__ void __launch_bounds__(128) gemm_kernel(const float* __restrict__ Xin,
                                                   const uint32_t* __restrict__ Bg,
                                                   const float* __restrict__ bias, int N) {
    constexpr int KC = KSTEPS * 8;          // real K (64 or 16)
    constexpr int AP = KC + 4;              // A row pitch (u32)
    constexpr int CHUNK_U32 = 4 * KSTEPS * 64;
    extern __shared__ uint32_t sm[];
    uint32_t* Asm = sm;                      // [128][AP]
    uint32_t* Bbuf = sm + 128 * AP;          // [2][CHUNK_U32]
    const uint32_t bbase = smem_u32(Bbuf);

    const int tid = threadIdx.x;
    const int wid = tid >> 5;
    const int lane = tid & 31;
    const int gID = lane >> 2;
    const int tig = lane & 3;
    const int n0 = blockIdx.x * 128;

    // Prefetch chunk 0 B.
    {
        constexpr int PT = CHUNK_U32 / (128 * 4);
        #pragma unroll
        for (int i = 0; i < PT; i++)
            cp_async16(bbase + (tid + i * 128) * 16, (const char*)Bg + (tid + i * 128) * 16);
        CP_COMMIT();
    }

    // Build this thread's A row (and run the fused per-node work).
    // Row n0+tid is exclusively owned by this thread; g_agg/g_deg/g_rt are
    // sized NCAP >= gridDim*128, so unguarded row writes are in-bounds.
    {
        const int n = n0 + tid;
        float4* aggp = reinterpret_cast<float4*>(g_agg + (size_t)n * 16);
        if (LAYER == 1) {
            const float4* xr = reinterpret_cast<const float4*>(Xin + (size_t)n * 64);
            #pragma unroll
            for (int c = 0; c < KC / 4; c++) {
                float4 f = (n < N) ? __ldg(xr + c) : make_float4(0.f, 0.f, 0.f, 0.f);
                Asm[tid * AP + 4 * c]     = f2tf32(f.x);
                Asm[tid * AP + 4 * c + 1] = f2tf32(f.y);
                Asm[tid * AP + 4 * c + 2] = f2tf32(f.z);
                Asm[tid * AP + 4 * c + 3] = f2tf32(f.w);
            }
            // Fused zero of agg + deg (runs before edge pass 1).
            float4 z = make_float4(0.f, 0.f, 0.f, 0.f);
            #pragma unroll
            for (int c = 0; c < 4; c++) aggp[c] = z;
            g_deg[n] = 0.0f;
        } else {
            // Fused node epilogue of layer 1: h = relu(agg/max(deg,1) + rt)
            float dg = g_deg[n];
            dg = dg > 1.0f ? dg : 1.0f;
            const float4* rtp = reinterpret_cast<const float4*>(g_rt + (size_t)n * 16);
            #pragma unroll
            for (int c = 0; c < 4; c++) {
                float4 ag = (n < N) ? aggp[c] : make_float4(0.f, 0.f, 0.f, 0.f);
                float4 rt = (n < N) ? rtp[c] : make_float4(0.f, 0.f, 0.f, 0.f);
                float h0 = ag.x / dg + rt.x; h0 = h0 > 0.f ? h0 : 0.f;
                float h1 = ag.y / dg + rt.y; h1 = h1 > 0.f ? h1 : 0.f;
                float h2 = ag.z / dg + rt.z; h2 = h2 > 0.f ? h2 : 0.f;
                float h3 = ag.w / dg + rt.w; h3 = h3 > 0.f ? h3 : 0.f;
                Asm[tid * AP + 4 * c]     = f2tf32(h0);
                Asm[tid * AP + 4 * c + 1] = f2tf32(h1);
                Asm[tid * AP + 4 * c + 2] = f2tf32(h2);
                Asm[tid * AP + 4 * c + 3] = f2tf32(h3);
            }
            // Re-zero agg for layer-2 edge pass (read-before-write, row-exclusive).
            float4 z = make_float4(0.f, 0.f, 0.f, 0.f);
            #pragma unroll
            for (int c = 0; c < 4; c++) aggp[c] = z;
        }
    }
    __syncthreads();

    // A fragments: [mtile][kstep][4]
    uint32_t a[2][KSTEPS][4];
    #pragma unroll
    for (int mt = 0; mt < 2; mt++) {
        int r0 = wid * 32 + mt * 16 + gID;
        #pragma unroll
        for (int ks = 0; ks < KSTEPS; ks++) {
            a[mt][ks][0] = Asm[r0 * AP + ks * 8 + tig];
            a[mt][ks][1] = Asm[(r0 + 8) * AP + ks * 8 + tig];
            a[mt][ks][2] = Asm[r0 * AP + ks * 8 + tig + 4];
            a[mt][ks][3] = Asm[(r0 + 8) * AP + ks * 8 + tig + 4];
        }
    }

    #pragma unroll 1
    for (int chunk = 0; chunk < 13; chunk++) {
        if (chunk + 1 < 13) {
            constexpr int PT = CHUNK_U32 / (128 * 4);
            uint32_t dst = bbase + ((chunk + 1) & 1) * (CHUNK_U32 * 4);
            const char* src = (const char*)(Bg + (size_t)(chunk + 1) * CHUNK_U32);
            #pragma unroll
            for (int i = 0; i < PT; i++)
                cp_async16(dst + (tid + i * 128) * 16, src + (tid + i * 128) * 16);
        }
        CP_COMMIT();
        CP_WAIT1();
        __syncthreads();

        const uint32_t* bb = Bbuf + (chunk & 1) * CHUNK_U32;
        float c[2][4][4];
        #pragma unroll
        for (int mt = 0; mt < 2; mt++)
            #pragma unroll
            for (int nt = 0; nt < 4; nt++)
                #pragma unroll
                for (int r = 0; r < 4; r++) c[mt][nt][r] = 0.0f;

        #pragma unroll
        for (int ks = 0; ks < KSTEPS; ks++)
            #pragma unroll
            for (int nt = 0; nt < 4; nt++) {
                uint2 b = *reinterpret_cast<const uint2*>(bb + (nt * KSTEPS + ks) * 64 + lane * 2);
                mma_tf32(c[0][nt], a[0][ks], b.x, b.y);
                mma_tf32(c[1][nt], a[1][ks], b.x, b.y);
            }
        __syncthreads();  // all warps done with this buffer before re-fill

        // Epilogue for this chunk.
        #pragma unroll
        for (int mt = 0; mt < 2; mt++)
            #pragma unroll
            for (int nt = 0; nt < 4; nt++) {
                int col = chunk * 32 + nt * 8 + tig * 2;
                int row0 = n0 + wid * 32 + mt * 16 + gID;
                int row1 = row0 + 8;
                float* cc = c[mt][nt];
                if (col < 400) {
                    if (row0 < N)
                        *reinterpret_cast<__half2*>(g_y + (size_t)row0 * 400 + col) =
                            __floats2half2_rn(cc[0], cc[1]);
                    if (row1 < N)
                        *reinterpret_cast<__half2*>(g_y + (size_t)row1 * 400 + col) =
                            __floats2half2_rn(cc[2], cc[3]);
                } else {
                    int o = col - 400;
                    float bv0 = __ldg(bias + o), bv1 = __ldg(bias + o + 1);
                    if (row0 < N) {
                        g_rt[(size_t)row0 * 16 + o] = cc[0] + bv0;
                        g_rt[(size_t)row0 * 16 + o + 1] = cc[1] + bv1;
                    }
                    if (row1 < N) {
                        g_rt[(size_t)row1 * 16 + o] = cc[2] + bv0;
                        g_rt[(size_t)row1 * 16 + o + 1] = cc[3] + bv1;
                    }
                }
            }
    }
}

// ---------------- edge kernel (2 lanes/edge) ----------------
__global__ void edge_kernel(const int* __restrict__ src, const int* __restrict__ dst,
                            const float* __restrict__ pseudo, int E, int addDeg) {
    int t = blockIdx.x * blockDim.x + threadIdx.x;
    int e = t >> 1;
    if (e >= E) return;
    int q = t & 1;
    int s = __ldg(src + e);
    int d = __ldg(dst + e);
    float2 p = __ldg(reinterpret_cast<const float2*>(pseudo) + e);
    float v0 = p.x * 4.0f, v1 = p.y * 4.0f;
    float fl0 = floorf(v0), fl1 = floorf(v1);
    float f0 = v0 - fl0, f1 = v1 - fl1;
    int i0 = (int)fl0, i1 = (int)fl1;
    int i0b = i0 + 1; if (i0b >= 5) i0b = 0;
    int i1b = i1 + 1; if (i1b >= 5) i1b = 0;
    float g0 = 1.0f - f0, g1 = 1.0f - f1;
    float w00 = g0 * g1, w10 = f0 * g1, w01 = g0 * f1, w11 = f0 * f1;

    const uint4* yb = reinterpret_cast<const uint4*>(g_y + (size_t)s * 400);
    uint4 c00 = __ldg(yb + ((i1  * 5 + i0 ) * 2 + q));
    uint4 c10 = __ldg(yb + ((i1  * 5 + i0b) * 2 + q));
    uint4 c01 = __ldg(yb + ((i1b * 5 + i0 ) * 2 + q));
    uint4 c11 = __ldg(yb + ((i1b * 5 + i0b) * 2 + q));

    float m[8];
    #pragma unroll
    for (int j = 0; j < 4; j++) {
        float2 a = __half22float2(*reinterpret_cast<const __half2*>(((const unsigned*)&c00) + j));
        float2 b = __half22float2(*reinterpret_cast<const __half2*>(((const unsigned*)&c10) + j));
        float2 c = __half22float2(*reinterpret_cast<const __half2*>(((const unsigned*)&c01) + j));
        float2 dd = __half22float2(*reinterpret_cast<const __half2*>(((const unsigned*)&c11) + j));
        m[2 * j + 0] = w00 * a.x + w10 * b.x + w01 * c.x + w11 * dd.x;
        m[2 * j + 1] = w00 * a.y + w10 * b.y + w01 * c.y + w11 * dd.y;
    }

    float* ap = g_agg + (size_t)d * 16 + q * 8;
    red_add_v4(ap,     m[0], m[1], m[2], m[3]);
    red_add_v4(ap + 4, m[4], m[5], m[6], m[7]);
    if (addDeg && q == 0) atomicAdd(g_deg + d, 1.0f);
}

// Final output: out = agg/max(deg,1) + rt
__global__ void node_final_kernel(float* __restrict__ out, int N) {
    int i = blockIdx.x * blockDim.x + threadIdx.x;
    if (i >= N * 16) return;
    float dg = g_deg[i >> 4];
    dg = dg > 1.0f ? dg : 1.0f;
    out[i] = g_agg[i] / dg + g_rt[i];
}

extern "C" void kernel_launch(void* const* d_in, const int* in_sizes, int n_in,
                              void* d_out, int out_size) {
    const float* x      = (const float*)d_in[0];
    const int*   ei     = (const int*)  d_in[1];
    const float* pseudo = (const float*)d_in[2];
    const float* W1     = (const float*)d_in[3];
    const float* root1  = (const float*)d_in[4];
    const float* b1     = (const float*)d_in[5];
    const float* W2     = (const float*)d_in[6];
    const float* root2  = (const float*)d_in[7];
    const float* b2     = (const float*)d_in[8];
    float* out = (float*)d_out;

    int N = in_sizes[0] / 64;
    int E = in_sizes[1] / 2;
    if (N > NCAP) N = NCAP;     // NCAP is a multiple of 128: grid rows <= NCAP, arrays sized NCAP
    const int* src = ei;
    const int* dst = ei + E;

    // smem: layer1 = 128*68*4 + 2*2048*4 = 51200; layer2 = 128*20*4 + 2*512*4 = 14336
    const int smem1 = 51200, smem2 = 14336;
    static uint32_t *B1p = nullptr, *B2p = nullptr;
    if (!B1p) {
        cudaGetSymbolAddress((void**)&B1p, g_B1);
        cudaGetSymbolAddress((void**)&B2p, g_B2);
        cudaFuncSetAttribute((const void*)gemm_kernel<1, 8>,
                             cudaFuncAttributeMaxDynamicSharedMemorySize, smem1);
        cudaFuncSetAttribute((const void*)gemm_kernel<2, 2>,
                             cudaFuncAttributeMaxDynamicSharedMemorySize, smem2);
    }

    int nodeGrid = (N * 16 + 255) / 256;
    int edgeGrid = (E * 2 + 255) / 256;
    int gemmGrid = (N + 127) / 128;

    prepB_kernel<64, 8><<<(52 * 8 * 64 + 255) / 256, 256>>>(W1, root1, B1p);
    prepB_kernel<16, 2><<<(52 * 2 * 64 + 255) / 256, 256>>>(W2, root2, B2p);
    // ---- Layer 1 (gemm zeroes agg+deg for edge pass 1) ----
    gemm_kernel<1, 8><<<gemmGrid, 128, smem1>>>(x, B1p, b1, N);
    edge_kernel<<<edgeGrid, 256>>>(src, dst, pseudo, E, 1);
    // ---- Layer 2 (gemm consumes layer-1 agg inline, re-zeroes agg) ----
    gemm_kernel<2, 2><<<gemmGrid, 128, smem2>>>(nullptr, B2p, b2, N);
    edge_kernel<<<edgeGrid, 256>>>(src, dst, pseudo, E, 0);
    node_final_kernel<<<nodeGrid, 256>>>(out, N);
}